// round 10
// baseline (speedup 1.0000x reference)
#include <cuda_runtime.h>
#include <cuda_fp16.h>
#include <cstdint>

#define Bn   64
#define Sn   1024
#define Dn   1024
#define NT   34      // tags incl BOS
#define NA   33      // active states (BOS column dead)
#define BOSI 33
#define NP   40      // padded N (5 x n8)

typedef uint32_t u32;

// -------- scratch (static device allocations) --------
__device__ float  g_exp_proj[(size_t)Bn * NA * Sn];  // [b][j][t] exp(proj)
__device__ u32    g_Wp0[512 * NP];                   // W hi as f16x2 pairs along k: [k/2][40]
__device__ u32    g_Wp1[512 * NP];                   // W lo
__device__ float  g_pm[Bn][NA];                      // forward p at mid
__device__ float  g_vm[Bn][NA];                      // backward v at mid
__device__ int    g_cntf[Bn], g_cntb[Bn];
__device__ float  g_score[Bn];

// ============================ prep: split W into f16 hi/lo fragment layout ============================
__global__ __launch_bounds__(1024)
void prep_kernel(const float* __restrict__ W)
{
    int idx = blockIdx.x * 1024 + threadIdx.x;   // 20480 = 512 k2 x 40 n
    if (idx >= 512 * NP) return;
    int k2 = idx / NP, n = idx - k2 * NP;
    float w0 = (n < NA) ? W[(size_t)(2*k2)   * NT + n] : 0.f;
    float w1 = (n < NA) ? W[(size_t)(2*k2+1) * NT + n] : 0.f;
    __half2 h = __float22half2_rn(make_float2(w0, w1));     // lo = k even
    float2 hf = __half22float2(h);
    __half2 l = __float22half2_rn(make_float2(w0 - hf.x, w1 - hf.y));
    g_Wp0[idx] = *reinterpret_cast<u32*>(&h);
    g_Wp1[idx] = *reinterpret_cast<u32*>(&l);
}

// ============================ GEMM: mma.sync m16n8k16 f16, 3-term split ============================
// 512 CTAs x 128 thr (4 warps). CTA: 128 rows. Warp: 32 rows (2 m16 tiles). N=40 (5 n8).
#define KC 16

__device__ __forceinline__ void mma_f16(float* d, const u32* a, u32 b0, u32 b1){
    asm volatile("mma.sync.aligned.m16n8k16.row.col.f32.f16.f16.f32 "
        "{%0,%1,%2,%3}, {%4,%5,%6,%7}, {%8,%9}, {%0,%1,%2,%3};"
        : "+f"(d[0]), "+f"(d[1]), "+f"(d[2]), "+f"(d[3])
        : "r"(a[0]), "r"(a[1]), "r"(a[2]), "r"(a[3]), "r"(b0), "r"(b1));
}

__device__ __forceinline__ void split_pack(float2 f, u32& h_out, u32& l_out){
    __half2 h = __float22half2_rn(f);
    float2 hf = __half22float2(h);
    __half2 l = __float22half2_rn(make_float2(f.x - hf.x, f.y - hf.y));
    h_out = *reinterpret_cast<u32*>(&h);
    l_out = *reinterpret_cast<u32*>(&l);
}

__global__ __launch_bounds__(128, 4)
void gemm_kernel(const float* __restrict__ em, const float* __restrict__ bias,
                 float* __restrict__ out)
{
    __shared__ __align__(16) float As[128][20];    // 16 data + 4 pad
    __shared__ __align__(16) u32 Wps[2][8][NP];    // [hi/lo][k2][n]
    __shared__ float s_bias[NP];

    const int tid = threadIdx.x;
    const int wid = tid >> 5;
    const int lane = tid & 31;
    const int g  = lane >> 2;
    const int t4 = lane & 3;
    const int row_base = blockIdx.x * 128;

    if (tid < NP) s_bias[tid] = (tid < NA) ? bias[tid] : 0.f;

    float acc[2][5][4];
    #pragma unroll
    for (int mt = 0; mt < 2; mt++)
        #pragma unroll
        for (int nt = 0; nt < 5; nt++)
            #pragma unroll
            for (int q = 0; q < 4; q++) acc[mt][nt][q] = 0.f;

    for (int kt = 0; kt < Dn / KC; kt++){
        const int k0 = kt * KC;
        __syncthreads();
        {   // stage A: thread t loads row t, cols k0..k0+15
            const float4* src = (const float4*)(em + (size_t)(row_base + tid) * Dn + k0);
            float4* dst = (float4*)(&As[tid][0]);
            #pragma unroll
            for (int q = 0; q < 4; q++) dst[q] = src[q];
            // stage W fragments: 320 u32 each, contiguous
            const u32* s0 = g_Wp0 + kt * (8 * NP);
            const u32* s1 = g_Wp1 + kt * (8 * NP);
            u32* d0 = &Wps[0][0][0];
            u32* d1 = &Wps[1][0][0];
            #pragma unroll
            for (int i = tid; i < 8 * NP; i += 128){ d0[i] = s0[i]; d1[i] = s1[i]; }
        }
        __syncthreads();

        // B fragments (5 n-tiles, hi & lo) — conflict-free LDS.32
        u32 bh0[5], bh1[5], bl0[5], bl1[5];
        #pragma unroll
        for (int nt = 0; nt < 5; nt++){
            int n = nt * 8 + g;
            bh0[nt] = Wps[0][t4][n];
            bh1[nt] = Wps[0][t4 + 4][n];
            bl0[nt] = Wps[1][t4][n];
            bl1[nt] = Wps[1][t4 + 4][n];
        }
        #pragma unroll
        for (int mt = 0; mt < 2; mt++){
            int r = wid * 32 + mt * 16 + g;
            float2 x0 = *(const float2*)&As[r][2*t4];
            float2 x1 = *(const float2*)&As[r + 8][2*t4];
            float2 x2 = *(const float2*)&As[r][2*t4 + 8];
            float2 x3 = *(const float2*)&As[r + 8][2*t4 + 8];
            u32 ah[4], al[4];
            split_pack(x0, ah[0], al[0]);
            split_pack(x1, ah[1], al[1]);
            split_pack(x2, ah[2], al[2]);
            split_pack(x3, ah[3], al[3]);
            #pragma unroll
            for (int nt = 0; nt < 5; nt++){
                mma_f16(acc[mt][nt], ah, bh0[nt], bh1[nt]);
                mma_f16(acc[mt][nt], al, bh0[nt], bh1[nt]);
                mma_f16(acc[mt][nt], ah, bl0[nt], bl1[nt]);
            }
        }
    }

    // epilogue: d0:(g, 2t4), d1:(g, 2t4+1), d2:(g+8, 2t4), d3:(g+8, 2t4+1)
    #pragma unroll
    for (int mt = 0; mt < 2; mt++){
        int r0 = row_base + wid * 32 + mt * 16 + g;
        int r1 = r0 + 8;
        #pragma unroll
        for (int nt = 0; nt < 5; nt++){
            int c0 = nt * 8 + 2 * t4;
            int c1 = c0 + 1;
            float v00 = acc[mt][nt][0] + s_bias[c0];
            float v01 = acc[mt][nt][1] + s_bias[c1];
            float v10 = acc[mt][nt][2] + s_bias[c0];
            float v11 = acc[mt][nt][3] + s_bias[c1];
            int b0 = r0 >> 10, s0 = r0 & 1023;
            int b1 = r1 >> 10, s1 = r1 & 1023;
            if (c0 < NA){
                out[1 + (size_t)r0 * NA + c0] = v00;
                out[1 + (size_t)r1 * NA + c0] = v10;
                g_exp_proj[((size_t)b0 * NA + c0) * Sn + s0] = __expf(v00);
                g_exp_proj[((size_t)b1 * NA + c0) * Sn + s1] = __expf(v10);
            }
            if (c1 < NA){
                out[1 + (size_t)r0 * NA + c1] = v01;
                out[1 + (size_t)r1 * NA + c1] = v11;
                g_exp_proj[((size_t)b0 * NA + c1) * Sn + s0] = __expf(v01);
                g_exp_proj[((size_t)b1 * NA + c1) * Sn + s1] = __expf(v11);
            }
        }
    }
}

// ============================ CRF scan (fwd/bwd) + gold score, one kernel ============================
#define SCAN_BODY(PL, PH, EMJ, EM32, MK, DOT_W)                                \
{                                                                              \
    float p0v = __shfl_sync(0xffffffffu, PL, 0);                               \
    unsigned eb = __float_as_uint(p0v) >> 23;                                  \
    cnt += (int)eb - 127;                                                      \
    float scl = __uint_as_float((254u - eb) << 23);                            \
    float al0=0.f, al1=0.f, al2=0.f, al3=0.f;                                  \
    float ahh0=0.f, ahh1=0.f, ahh2=0.f, ahh3=0.f;                              \
    float wl = (DOT_W) ? (PL) * (EMJ)  : (PL);                                 \
    float wh = (DOT_W) ? (PH) * (EM32) : (PH);                                 \
    _Pragma("unroll")                                                          \
    for (int i = 0; i < 32; i += 4){                                           \
        float v0 = __shfl_sync(0xffffffffu, wl, i);                            \
        float v1 = __shfl_sync(0xffffffffu, wl, i+1);                          \
        float v2 = __shfl_sync(0xffffffffu, wl, i+2);                          \
        float v3 = __shfl_sync(0xffffffffu, wl, i+3);                          \
        al0 += v0*E_l[i];   ahh0 += v0*E_h[i];                                 \
        al1 += v1*E_l[i+1]; ahh1 += v1*E_h[i+1];                               \
        al2 += v2*E_l[i+2]; ahh2 += v2*E_h[i+2];                               \
        al3 += v3*E_l[i+3]; ahh3 += v3*E_h[i+3];                               \
    }                                                                          \
    al0 += wh*E_l[32]; ahh0 += wh*E_h[32];                                     \
    float sl = (al0+al1)+(al2+al3);                                            \
    float sh = (ahh0+ahh1)+(ahh2+ahh3);                                        \
    float nl, nh;                                                              \
    if (DOT_W){ nl = sl*scl; nh = sh*scl; }                                    \
    else      { nl = sl*((EMJ)*scl); nh = sh*((EM32)*scl); }                   \
    if ((MK) == 0.f){ nl = (PL)*scl; nh = (PH)*scl; }                          \
    PL = nl; PH = nh;                                                          \
}

__global__ __launch_bounds__(32)
void scan_kernel(const float* __restrict__ T, const float* __restrict__ mask,
                 const int* __restrict__ tags, const float* __restrict__ out)
{
    const int blk = blockIdx.x;
    const int j   = threadIdx.x;

    if (blk >= 2 * Bn){
        // ---- gold-path score for batch (blk - 2*Bn) ----
        int b = blk - 2 * Bn, lane = j;
        float partial = 0.f;
        for (int t = lane; t < Sn; t += 32){
            int   tg = tags[b*Sn + t];
            float e  = out[1 + ((size_t)b*Sn + t)*NA + tg];
            if (t == 0){
                partial += T[BOSI*NT + tg] + e;
            } else {
                int tgp = tags[b*Sn + t - 1];
                partial += (e + T[tgp*NT + tg]) * mask[b*Sn + t];
            }
        }
        #pragma unroll
        for (int o = 16; o; o >>= 1) partial += __shfl_xor_sync(0xffffffffu, partial, o);
        if (lane == 0) g_score[b] = partial;
        return;
    }

    const int b   = blk >> 1;
    const int dir = blk & 1;

    float E_l[NA], E_h[NA];
    if (dir == 0){
        #pragma unroll
        for (int i = 0; i < NA; i++){
            E_l[i] = __expf(T[i*NT + j]);
            E_h[i] = __expf(T[i*NT + 32]);
        }
    } else {
        #pragma unroll
        for (int s = 0; s < NA; s++){
            E_l[s] = __expf(T[j*NT + s]);
            E_h[s] = __expf(T[32*NT + s]);
        }
    }

    const float4* epj  = (const float4*)(g_exp_proj + ((size_t)b*NA + j ) * Sn);
    const float4* ep32 = (const float4*)(g_exp_proj + ((size_t)b*NA + 32) * Sn);
    const float4* mp4  = (const float4*)(mask + (size_t)b * Sn);

    int cnt = 0;

    if (dir == 0){
        float4 e = epj[0], e32 = ep32[0], mk = mp4[0];
        float pl = __expf(T[BOSI*NT + j])  * e.x;
        float ph = __expf(T[BOSI*NT + 32]) * e32.x;

        SCAN_BODY(pl, ph, e.y, e32.y, mk.y, 0);
        SCAN_BODY(pl, ph, e.z, e32.z, mk.z, 0);
        SCAN_BODY(pl, ph, e.w, e32.w, mk.w, 0);
        for (int gq = 1; gq < 128; gq++){
            e = epj[gq]; e32 = ep32[gq]; mk = mp4[gq];
            SCAN_BODY(pl, ph, e.x, e32.x, mk.x, 0);
            SCAN_BODY(pl, ph, e.y, e32.y, mk.y, 0);
            SCAN_BODY(pl, ph, e.z, e32.z, mk.z, 0);
            SCAN_BODY(pl, ph, e.w, e32.w, mk.w, 0);
        }
        g_pm[b][j] = pl;
        if (j == 0){ g_pm[b][32] = ph; g_cntf[b] = cnt; }
    } else {
        float vl = 1.f, vh = 1.f;
        for (int gq = 255; gq >= 128; gq--){
            float4 e = epj[gq], e32 = ep32[gq], mk = mp4[gq];
            SCAN_BODY(vl, vh, e.w, e32.w, mk.w, 1);
            SCAN_BODY(vl, vh, e.z, e32.z, mk.z, 1);
            SCAN_BODY(vl, vh, e.y, e32.y, mk.y, 1);
            SCAN_BODY(vl, vh, e.x, e32.x, mk.x, 1);
        }
        g_vm[b][j] = vl;
        if (j == 0){ g_vm[b][32] = vh; g_cntb[b] = cnt; }
    }
}

// ============================ combine + loss ============================
__global__ __launch_bounds__(64)
void loss_kernel(float* __restrict__ out)
{
    __shared__ double red[64];
    int b = threadIdx.x;
    double dot = 0.0;
    #pragma unroll
    for (int i = 0; i < NA; i++) dot += (double)g_pm[b][i] * (double)g_vm[b][i];
    double part = (double)(g_cntf[b] + g_cntb[b]) * 0.6931471805599453 + log(dot);
    red[b] = part - (double)g_score[b];
    __syncthreads();
    if (b == 0){
        double s = 0.0;
        #pragma unroll
        for (int i = 0; i < 64; i++) s += red[i];
        out[0] = (float)s;
    }
}

// ============================ launch ============================
extern "C" void kernel_launch(void* const* d_in, const int* in_sizes, int n_in,
                              void* d_out, int out_size)
{
    const float* em   = (const float*)d_in[0];   // (B,S,D)
    const int*   tags = (const int*)  d_in[1];   // (B,S)
    const float* mask = (const float*)d_in[2];   // (B,S)
    const float* W    = (const float*)d_in[3];   // (D,N)
    const float* bias = (const float*)d_in[4];   // (N,)
    const float* T    = (const float*)d_in[5];   // (N,N)
    float* out = (float*)d_out;                  // [loss, logits(B,S,33)]

    prep_kernel <<<20, 1024>>>(W);
    gemm_kernel <<<(Bn*Sn)/128, 128>>>(em, bias, out);
    scan_kernel <<<3*Bn, 32>>>(T, mask, tags, out);
    loss_kernel <<<1, 64>>>(out);
}

// round 11
// speedup vs baseline: 1.2313x; 1.2313x over previous
#include <cuda_runtime.h>
#include <cstdint>

#define Bn   64
#define Sn   1024
#define Dn   1024
#define NT   34      // tags incl BOS
#define NA   33      // active states (BOS column dead)
#define BOSI 33

// -------- scratch (static device allocations) --------
__device__ float  g_exp_proj[(size_t)Bn * NA * Sn];  // [b][j][t] exp(proj)
__device__ float  g_pm[Bn][NA];                      // forward p at mid
__device__ float  g_vm[Bn][NA];                      // backward v at mid
__device__ int    g_cntf[Bn], g_cntb[Bn];
__device__ float  g_score[Bn];

// ============================ GEMM: scalar FFMA, software-pipelined ============================
// 1024 CTAs x 64 threads, 1 row/thread, KT=16. W double-buffered in smem via
// registers (LDG early, STS after compute, 1 barrier/tile). A double-buffered
// in registers. Epilogue: logits staged through smem for coalesced stores.
#define KT2 16

#define GU(AV, KK) do{                                                     \
    const float4* wr_ = (const float4*)(&Wt[cur][KK][0]);                  \
    float4 w0_=wr_[0], w1_=wr_[1], w2_=wr_[2], w3_=wr_[3];                 \
    float4 w4_=wr_[4], w5_=wr_[5], w6_=wr_[6], w7_=wr_[7];                 \
    float  wl_ = Wt[cur][KK][32];                                          \
    acc[0] += (AV)*w0_.x; acc[1] += (AV)*w0_.y; acc[2] += (AV)*w0_.z; acc[3] += (AV)*w0_.w; \
    acc[4] += (AV)*w1_.x; acc[5] += (AV)*w1_.y; acc[6] += (AV)*w1_.z; acc[7] += (AV)*w1_.w; \
    acc[8] += (AV)*w2_.x; acc[9] += (AV)*w2_.y; acc[10]+= (AV)*w2_.z; acc[11]+= (AV)*w2_.w; \
    acc[12]+= (AV)*w3_.x; acc[13]+= (AV)*w3_.y; acc[14]+= (AV)*w3_.z; acc[15]+= (AV)*w3_.w; \
    acc[16]+= (AV)*w4_.x; acc[17]+= (AV)*w4_.y; acc[18]+= (AV)*w4_.z; acc[19]+= (AV)*w4_.w; \
    acc[20]+= (AV)*w5_.x; acc[21]+= (AV)*w5_.y; acc[22]+= (AV)*w5_.z; acc[23]+= (AV)*w5_.w; \
    acc[24]+= (AV)*w6_.x; acc[25]+= (AV)*w6_.y; acc[26]+= (AV)*w6_.z; acc[27]+= (AV)*w6_.w; \
    acc[28]+= (AV)*w7_.x; acc[29]+= (AV)*w7_.y; acc[30]+= (AV)*w7_.z; acc[31]+= (AV)*w7_.w; \
    acc[32]+= (AV)*wl_;                                                    \
} while(0)

__global__ __launch_bounds__(64, 8)
void gemm_kernel(const float* __restrict__ em, const float* __restrict__ W,
                 const float* __restrict__ bias, float* __restrict__ out)
{
    __shared__ __align__(16) float Wt[2][KT2][36];
    __shared__ float s_bias[NA];
    __shared__ float s_out[64 * NA];

    const int tid = threadIdx.x;
    const int row = blockIdx.x * 64 + tid;

    if (tid < NA) s_bias[tid] = bias[tid];

    float acc[NA];
    #pragma unroll
    for (int j = 0; j < NA; j++) acc[j] = 0.f;

    const float4* arow = (const float4*)(em + (size_t)row * Dn);

    float4 abuf[2][4];

    // initial stage: W tile 0 -> Wt[0], A tile 0 -> abuf[0]
    #pragma unroll
    for (int q = 0; q < 9; q++){
        int i = tid + 64*q;                 // 0..575
        int kk = i / 36, j = i - kk*36;
        (&Wt[0][0][0])[i] = (j < NA) ? W[(size_t)kk * NT + j] : 0.f;
    }
    #pragma unroll
    for (int q = 0; q < 4; q++) abuf[0][q] = arow[q];
    __syncthreads();

    #pragma unroll 2
    for (int kt = 0; kt < Dn/KT2; kt++){
        const int cur = kt & 1, nxt = cur ^ 1;
        float wreg[9];
        const bool more = (kt < Dn/KT2 - 1);
        if (more){
            const float* wsrc = W + (size_t)(kt+1) * KT2 * NT;
            #pragma unroll
            for (int q = 0; q < 9; q++){
                int i = tid + 64*q;
                int kk = i / 36, j = i - kk*36;
                wreg[q] = (j < NA) ? wsrc[(size_t)kk * NT + j] : 0.f;
            }
            const float4* asrc = arow + (kt+1) * (KT2/4);
            #pragma unroll
            for (int q = 0; q < 4; q++) abuf[nxt][q] = asrc[q];
        }

        #pragma unroll
        for (int kk4 = 0; kk4 < 4; kk4++){
            float4 av = abuf[cur][kk4];
            GU(av.x, kk4*4+0);
            GU(av.y, kk4*4+1);
            GU(av.z, kk4*4+2);
            GU(av.w, kk4*4+3);
        }

        if (more){
            #pragma unroll
            for (int q = 0; q < 9; q++)
                (&Wt[nxt][0][0])[tid + 64*q] = wreg[q];
            __syncthreads();
        }
    }

    // epilogue
    const int b = row >> 10, s = row & 1023;
    #pragma unroll
    for (int j = 0; j < NA; j++){
        float v = acc[j] + s_bias[j];
        s_out[tid * NA + j] = v;                                  // stride 33: conflict-free
        g_exp_proj[((size_t)b * NA + j) * Sn + s] = __expf(v);    // coalesced per j
    }
    __syncthreads();
    float* obase = out + 1 + (size_t)blockIdx.x * 64 * NA;
    #pragma unroll
    for (int q = 0; q < NA; q++)
        obase[tid + 64*q] = s_out[tid + 64*q];                    // coalesced
}

// ============================ CRF scan (fwd/bwd) + gold score, one kernel ============================
#define SCAN_BODY(PL, PH, EMJ, EM32, MK, DOT_W)                                \
{                                                                              \
    float p0v = __shfl_sync(0xffffffffu, PL, 0);                               \
    unsigned eb = __float_as_uint(p0v) >> 23;                                  \
    cnt += (int)eb - 127;                                                      \
    float scl = __uint_as_float((254u - eb) << 23);                            \
    float al0=0.f, al1=0.f, al2=0.f, al3=0.f;                                  \
    float ahh0=0.f, ahh1=0.f, ahh2=0.f, ahh3=0.f;                              \
    float wl = (DOT_W) ? (PL) * (EMJ)  : (PL);                                 \
    float wh = (DOT_W) ? (PH) * (EM32) : (PH);                                 \
    _Pragma("unroll")                                                          \
    for (int i = 0; i < 32; i += 4){                                           \
        float v0 = __shfl_sync(0xffffffffu, wl, i);                            \
        float v1 = __shfl_sync(0xffffffffu, wl, i+1);                          \
        float v2 = __shfl_sync(0xffffffffu, wl, i+2);                          \
        float v3 = __shfl_sync(0xffffffffu, wl, i+3);                          \
        al0 += v0*E_l[i];   ahh0 += v0*E_h[i];                                 \
        al1 += v1*E_l[i+1]; ahh1 += v1*E_h[i+1];                               \
        al2 += v2*E_l[i+2]; ahh2 += v2*E_h[i+2];                               \
        al3 += v3*E_l[i+3]; ahh3 += v3*E_h[i+3];                               \
    }                                                                          \
    al0 += wh*E_l[32]; ahh0 += wh*E_h[32];                                     \
    float sl = (al0+al1)+(al2+al3);                                            \
    float sh = (ahh0+ahh1)+(ahh2+ahh3);                                        \
    float nl, nh;                                                              \
    if (DOT_W){ nl = sl*scl; nh = sh*scl; }                                    \
    else      { nl = sl*((EMJ)*scl); nh = sh*((EM32)*scl); }                   \
    if ((MK) == 0.f){ nl = (PL)*scl; nh = (PH)*scl; }                          \
    PL = nl; PH = nh;                                                          \
}

__global__ __launch_bounds__(32)
void scan_kernel(const float* __restrict__ T, const float* __restrict__ mask,
                 const int* __restrict__ tags, const float* __restrict__ out)
{
    const int blk = blockIdx.x;
    const int j   = threadIdx.x;

    if (blk >= 2 * Bn){
        // ---- gold-path score for batch (blk - 2*Bn) ----
        int b = blk - 2 * Bn, lane = j;
        float partial = 0.f;
        for (int t = lane; t < Sn; t += 32){
            int   tg = tags[b*Sn + t];
            float e  = out[1 + ((size_t)b*Sn + t)*NA + tg];
            if (t == 0){
                partial += T[BOSI*NT + tg] + e;
            } else {
                int tgp = tags[b*Sn + t - 1];
                partial += (e + T[tgp*NT + tg]) * mask[b*Sn + t];
            }
        }
        #pragma unroll
        for (int o = 16; o; o >>= 1) partial += __shfl_xor_sync(0xffffffffu, partial, o);
        if (lane == 0) g_score[b] = partial;
        return;
    }

    const int b   = blk >> 1;
    const int dir = blk & 1;

    float E_l[NA], E_h[NA];
    if (dir == 0){
        #pragma unroll
        for (int i = 0; i < NA; i++){
            E_l[i] = __expf(T[i*NT + j]);
            E_h[i] = __expf(T[i*NT + 32]);
        }
    } else {
        #pragma unroll
        for (int s = 0; s < NA; s++){
            E_l[s] = __expf(T[j*NT + s]);
            E_h[s] = __expf(T[32*NT + s]);
        }
    }

    const float4* epj  = (const float4*)(g_exp_proj + ((size_t)b*NA + j ) * Sn);
    const float4* ep32 = (const float4*)(g_exp_proj + ((size_t)b*NA + 32) * Sn);
    const float4* mp4  = (const float4*)(mask + (size_t)b * Sn);

    int cnt = 0;

    if (dir == 0){
        float4 e = epj[0], e32 = ep32[0], mk = mp4[0];
        float pl = __expf(T[BOSI*NT + j])  * e.x;
        float ph = __expf(T[BOSI*NT + 32]) * e32.x;

        SCAN_BODY(pl, ph, e.y, e32.y, mk.y, 0);
        SCAN_BODY(pl, ph, e.z, e32.z, mk.z, 0);
        SCAN_BODY(pl, ph, e.w, e32.w, mk.w, 0);
        for (int gq = 1; gq < 128; gq++){
            e = epj[gq]; e32 = ep32[gq]; mk = mp4[gq];
            SCAN_BODY(pl, ph, e.x, e32.x, mk.x, 0);
            SCAN_BODY(pl, ph, e.y, e32.y, mk.y, 0);
            SCAN_BODY(pl, ph, e.z, e32.z, mk.z, 0);
            SCAN_BODY(pl, ph, e.w, e32.w, mk.w, 0);
        }
        g_pm[b][j] = pl;
        if (j == 0){ g_pm[b][32] = ph; g_cntf[b] = cnt; }
    } else {
        float vl = 1.f, vh = 1.f;
        for (int gq = 255; gq >= 128; gq--){
            float4 e = epj[gq], e32 = ep32[gq], mk = mp4[gq];
            SCAN_BODY(vl, vh, e.w, e32.w, mk.w, 1);
            SCAN_BODY(vl, vh, e.z, e32.z, mk.z, 1);
            SCAN_BODY(vl, vh, e.y, e32.y, mk.y, 1);
            SCAN_BODY(vl, vh, e.x, e32.x, mk.x, 1);
        }
        g_vm[b][j] = vl;
        if (j == 0){ g_vm[b][32] = vh; g_cntb[b] = cnt; }
    }
}

// ============================ combine + loss ============================
__global__ __launch_bounds__(32)
void loss_kernel(float* __restrict__ out)
{
    int lane = threadIdx.x;
    double v = 0.0;
    #pragma unroll
    for (int h = 0; h < 2; h++){
        int b = lane + 32*h;
        double dot = 0.0;
        #pragma unroll
        for (int i = 0; i < NA; i++) dot += (double)g_pm[b][i] * (double)g_vm[b][i];
        double part = (double)(g_cntf[b] + g_cntb[b]) * 0.6931471805599453 + log(dot);
        v += part - (double)g_score[b];
    }
    #pragma unroll
    for (int o = 16; o; o >>= 1) v += __shfl_xor_sync(0xffffffffu, v, o);
    if (lane == 0) out[0] = (float)v;
}

// ============================ launch ============================
extern "C" void kernel_launch(void* const* d_in, const int* in_sizes, int n_in,
                              void* d_out, int out_size)
{
    const float* em   = (const float*)d_in[0];   // (B,S,D)
    const int*   tags = (const int*)  d_in[1];   // (B,S)
    const float* mask = (const float*)d_in[2];   // (B,S)
    const float* W    = (const float*)d_in[3];   // (D,N)
    const float* bias = (const float*)d_in[4];   // (N,)
    const float* T    = (const float*)d_in[5];   // (N,N)
    float* out = (float*)d_out;                  // [loss, logits(B,S,33)]

    gemm_kernel <<<(Bn*Sn)/64, 64>>>(em, W, bias, out);
    scan_kernel <<<3*Bn, 32>>>(T, mask, tags, out);
    loss_kernel <<<1, 32>>>(out);
}